// round 6
// baseline (speedup 1.0000x reference)
#include <cuda_runtime.h>
#include <cuda_bf16.h>
#include <cstdint>

#define B_TOTAL 4096
#define T 28
#define IN_F 28
#define H 128
#define L 10
#define C 10
#define BT 32
#define NBLK 128   // 4096/32

typedef uint32_t u32;

// Inter-layer activation planes: verbatim swizzled-SMEM tile images, ping-pong.
__device__ uint4 g_hi[2][NBLK * T * 512];
__device__ uint4 g_lo[2][NBLK * T * 512];
// Input-projection fragments: per step, 256 threads x 4 float4 (bias included).
__device__ float4 g_xp[NBLK * T * 1024];

// ---- SMEM byte offsets ----
#define O_WIH_HI 0
#define O_WIH_LO 32768
#define O_WHH_HI 65536
#define O_WHH_LO 98304
#define O_X0_HI 131072
#define O_X0_LO 139264
#define O_X1_HI 147456
#define O_X1_LO 155648
#define O_H_HI  163840
#define O_H_LO  172032
#define O_HF    180224
#define SMEM_BYTES 196608

static __device__ __forceinline__ u32 smem_u32(const void* p) {
    u32 a;
    asm("{ .reg .u64 t; cvta.to.shared.u64 t, %1; cvt.u32.u64 %0, t; }" : "=r"(a) : "l"(p));
    return a;
}
// XOR-swizzled [row][128 bf16] tile: 16B chunk c of row r lives at chunk (c ^ (r&7)).
static __device__ __forceinline__ u32 swz(int row, int col) {
    return (u32)(row * 256 + ((((col >> 3) ^ (row & 7))) << 4) + (col & 7) * 2);
}
static __device__ __forceinline__ void ldsm4(u32 r[4], u32 a) {
    asm volatile("ldmatrix.sync.aligned.m8n8.x4.shared.b16 {%0,%1,%2,%3}, [%4];"
                 : "=r"(r[0]), "=r"(r[1]), "=r"(r[2]), "=r"(r[3]) : "r"(a));
}
static __device__ __forceinline__ void ldsm2(u32 r[2], u32 a) {
    asm volatile("ldmatrix.sync.aligned.m8n8.x2.shared.b16 {%0,%1}, [%2];"
                 : "=r"(r[0]), "=r"(r[1]) : "r"(a));
}
static __device__ __forceinline__ void mma16816(float c[4], const u32 a[4], const u32 b[2]) {
    asm volatile(
        "mma.sync.aligned.m16n8k16.row.col.f32.bf16.bf16.f32 "
        "{%0,%1,%2,%3}, {%4,%5,%6,%7}, {%8,%9}, {%0,%1,%2,%3};"
        : "+f"(c[0]), "+f"(c[1]), "+f"(c[2]), "+f"(c[3])
        : "r"(a[0]), "r"(a[1]), "r"(a[2]), "r"(a[3]), "r"(b[0]), "r"(b[1]));
}
static __device__ __forceinline__ void bf16_split(float v, __nv_bfloat16& hh, __nv_bfloat16& ll) {
    hh = __float2bfloat16(v);
    ll = __float2bfloat16(v - __bfloat162float(hh));
}

__global__ void __launch_bounds__(256, 1)
rnn_mma(const float* __restrict__ x, const float* __restrict__ Wih0,
        const float* __restrict__ Wih, const float* __restrict__ Whh,
        const float* __restrict__ bih, const float* __restrict__ bhh,
        const float* __restrict__ fcW, const float* __restrict__ fcb,
        float* __restrict__ out) {
    extern __shared__ __align__(256) char smem[];
    const u32 sbase = smem_u32(smem);
    const int tid = threadIdx.x;
    const int wid = tid >> 5, lane = tid & 31;
    const int g = lane >> 2, tg = lane & 3;
    const int hc0 = wid * 16;                 // this warp's 16 h-columns
    const int l15 = lane & 15;
    const int arow = lane & 15;
    const int acol = ((lane >> 4) & 1) * 8;
    const int bBase = blockIdx.x * BT;

    // zero X buffers once (layer-0 pad cols stay zero; later layers overwrite fully)
    {
        uint4 z = make_uint4(0, 0, 0, 0);
        uint4* xb = (uint4*)(smem + O_X0_HI);
        for (int i = tid; i < 2048; i += 256) xb[i] = z;
    }
    const int hcol0 = hc0 + tg * 2;
    const int hcol2 = hc0 + 8 + tg * 2;

#pragma unroll 1
    for (int layer = 0; layer < L; ++layer) {
        __syncthreads();   // previous layer fully done

        // ---- stage weights (bf16 hi/lo) into swizzled tiles ----
        if (layer == 0) {
            for (int i = tid; i < H * H; i += 256) {
                int m = i >> 7, k = i & 127;
                float w = (k < IN_F) ? Wih0[m * IN_F + k] : 0.0f;
                __nv_bfloat16 hh, ll; bf16_split(w, hh, ll);
                u32 o = swz(m, k);
                *(__nv_bfloat16*)(smem + O_WIH_HI + o) = hh;
                *(__nv_bfloat16*)(smem + O_WIH_LO + o) = ll;
            }
        } else {
            const float* Wl = Wih + (layer - 1) * H * H;
            for (int i = tid; i < H * H; i += 256) {
                int m = i >> 7, k = i & 127;
                __nv_bfloat16 hh, ll; bf16_split(Wl[i], hh, ll);
                u32 o = swz(m, k);
                *(__nv_bfloat16*)(smem + O_WIH_HI + o) = hh;
                *(__nv_bfloat16*)(smem + O_WIH_LO + o) = ll;
            }
        }
        {
            const float* Wr = Whh + layer * H * H;
            for (int i = tid; i < H * H; i += 256) {
                int m = i >> 7, k = i & 127;
                __nv_bfloat16 hh, ll; bf16_split(Wr[i], hh, ll);
                u32 o = swz(m, k);
                *(__nv_bfloat16*)(smem + O_WHH_HI + o) = hh;
                *(__nv_bfloat16*)(smem + O_WHH_LO + o) = ll;
            }
        }
        const int rdp = (layer - 1) & 1, wrp = layer & 1;
        float bsum[4];
        bsum[0] = bih[layer * H + hcol0]     + bhh[layer * H + hcol0];
        bsum[1] = bih[layer * H + hcol0 + 1] + bhh[layer * H + hcol0 + 1];
        bsum[2] = bih[layer * H + hcol2]     + bhh[layer * H + hcol2];
        bsum[3] = bih[layer * H + hcol2 + 1] + bhh[layer * H + hcol2 + 1];

        // ---- stage t=0 input ----
        if (layer == 0) {
            for (int i = tid; i < BT * 32; i += 256) {
                int b = i >> 5, k = i & 31;
                if (k < IN_F) {
                    float v = x[((bBase + b) * T + 0) * IN_F + k];
                    __nv_bfloat16 hh, ll; bf16_split(v, hh, ll);
                    u32 o = swz(b, k);
                    *(__nv_bfloat16*)(smem + O_X0_HI + o) = hh;
                    *(__nv_bfloat16*)(smem + O_X0_LO + o) = ll;
                }
            }
        } else {
            const uint4* sh = g_hi[rdp] + (u32)(blockIdx.x * T) * 512;
            const uint4* sl = g_lo[rdp] + (u32)(blockIdx.x * T) * 512;
            uint4* dh = (uint4*)(smem + O_X0_HI);
            uint4* dl = (uint4*)(smem + O_X0_LO);
            for (int i = tid; i < 512; i += 256) { dh[i] = sh[i]; dl[i] = sl[i]; }
        }
        __syncthreads();

        // ======== PHASE A: input projections for all t (no recurrence) ========
        {
            u32 wih_hi[8][2][2], wih_lo[8][2][2];
#pragma unroll
            for (int kc = 0; kc < 8; ++kc)
#pragma unroll
                for (int nt = 0; nt < 2; ++nt) {
                    u32 o = swz(hc0 + nt * 8 + (l15 & 7), kc * 16 + ((l15 >> 3) << 3));
                    ldsm2(wih_hi[kc][nt], sbase + O_WIH_HI + o);
                    ldsm2(wih_lo[kc][nt], sbase + O_WIH_LO + o);
                }

#pragma unroll 1
            for (int t = 0; t < T; ++t) {
                const u32 xh = sbase + ((t & 1) ? O_X1_HI : O_X0_HI);
                const u32 xl = sbase + ((t & 1) ? O_X1_LO : O_X0_LO);
                float acc[2][2][4];
#pragma unroll
                for (int mt = 0; mt < 2; ++mt)
#pragma unroll
                    for (int nt = 0; nt < 2; ++nt)
#pragma unroll
                        for (int j = 0; j < 4; ++j)
                            acc[mt][nt][j] = bsum[nt * 2 + (j & 1)];

#pragma unroll
                for (int kc = 0; kc < 8; ++kc)
#pragma unroll
                    for (int mt = 0; mt < 2; ++mt) {
                        u32 ao = swz(mt * 16 + arow, kc * 16 + acol);
                        u32 axh[4], axl[4];
                        ldsm4(axh, xh + ao);
                        ldsm4(axl, xl + ao);
#pragma unroll
                        for (int nt = 0; nt < 2; ++nt) {
                            mma16816(acc[mt][nt], axh, wih_hi[kc][nt]);
                            mma16816(acc[mt][nt], axl, wih_hi[kc][nt]);
                            mma16816(acc[mt][nt], axh, wih_lo[kc][nt]);
                        }
                    }

                // stage next timestep's input while MMA drains
                if (t + 1 < T) {
                    const u32 nh = (t & 1) ? O_X0_HI : O_X1_HI;
                    if (layer == 0) {
                        for (int i = tid; i < BT * 32; i += 256) {
                            int b = i >> 5, k = i & 31;
                            if (k < IN_F) {
                                float v = x[((bBase + b) * T + t + 1) * IN_F + k];
                                __nv_bfloat16 hh, ll; bf16_split(v, hh, ll);
                                u32 o = swz(b, k);
                                *(__nv_bfloat16*)(smem + nh + o) = hh;
                                *(__nv_bfloat16*)(smem + nh + 8192 + o) = ll;
                            }
                        }
                    } else {
                        const uint4* sh2 = g_hi[rdp] + (u32)(blockIdx.x * T + t + 1) * 512;
                        const uint4* sl2 = g_lo[rdp] + (u32)(blockIdx.x * T + t + 1) * 512;
                        uint4* dh2 = (uint4*)(smem + nh);
                        uint4* dl2 = (uint4*)(smem + nh + 8192);
                        for (int i = tid; i < 512; i += 256) { dh2[i] = sh2[i]; dl2[i] = sl2[i]; }
                    }
                }

                // store xp fragments (coalesced 64B per thread)
                float4* dst = g_xp + (u32)(blockIdx.x * T + t) * 1024 + tid * 4;
                dst[0] = *(const float4*)acc[0][0];
                dst[1] = *(const float4*)acc[0][1];
                dst[2] = *(const float4*)acc[1][0];
                dst[3] = *(const float4*)acc[1][1];
                __syncthreads();   // next X staged; cur reads done before reuse
            }
        }

        // ======== PHASE B: recurrence ========
        {
            // zero hidden state tiles (t=0 recurrent mma contributes 0)
            uint4 z = make_uint4(0, 0, 0, 0);
            uint4* hb = (uint4*)(smem + O_H_HI);
            for (int i = tid; i < 1024; i += 256) hb[i] = z;

            u32 whh_hi[8][2][2], whh_lo[8][2][2];
#pragma unroll
            for (int kc = 0; kc < 8; ++kc)
#pragma unroll
                for (int nt = 0; nt < 2; ++nt) {
                    u32 o = swz(hc0 + nt * 8 + (l15 & 7), kc * 16 + ((l15 >> 3) << 3));
                    ldsm2(whh_hi[kc][nt], sbase + O_WHH_HI + o);
                    ldsm2(whh_lo[kc][nt], sbase + O_WHH_LO + o);
                }
            __syncthreads();   // sH zeros visible

#pragma unroll 1
            for (int t = 0; t < T; ++t) {
                // load xp fragments early (L2 hit), overlap with ldsm+mma
                const float4* src = g_xp + (u32)(blockIdx.x * T + t) * 1024 + tid * 4;
                float4 a0 = src[0], a1 = src[1], a2 = src[2], a3 = src[3];

                float acc[2][2][4];
                *(float4*)acc[0][0] = a0;
                *(float4*)acc[0][1] = a1;
                *(float4*)acc[1][0] = a2;
                *(float4*)acc[1][1] = a3;

                const u32 sh_hi = sbase + O_H_HI, sh_lo = sbase + O_H_LO;
#pragma unroll
                for (int kc = 0; kc < 8; ++kc)
#pragma unroll
                    for (int mt = 0; mt < 2; ++mt) {
                        u32 ao = swz(mt * 16 + arow, kc * 16 + acol);
                        u32 ahh[4], ahl[4];
                        ldsm4(ahh, sh_hi + ao);
                        ldsm4(ahl, sh_lo + ao);
#pragma unroll
                        for (int nt = 0; nt < 2; ++nt) {
                            mma16816(acc[mt][nt], ahh, whh_hi[kc][nt]);
                            mma16816(acc[mt][nt], ahl, whh_hi[kc][nt]);
                            mma16816(acc[mt][nt], ahh, whh_lo[kc][nt]);
                        }
                    }
                __syncthreads();   // S1: sH reads (mma + t-1 copy-out) complete

                // epilogue: tanh + write sH (hi/lo)
#pragma unroll
                for (int mt = 0; mt < 2; ++mt)
#pragma unroll
                    for (int bs = 0; bs < 2; ++bs) {
                        const int b = mt * 16 + bs * 8 + g;
#pragma unroll
                        for (int nt = 0; nt < 2; ++nt) {
                            float v0 = acc[mt][nt][bs * 2 + 0];
                            float v1 = acc[mt][nt][bs * 2 + 1];
                            float e0 = __expf(2.0f * v0);
                            float e1 = __expf(2.0f * v1);
                            v0 = 1.0f - __fdividef(2.0f, e0 + 1.0f);
                            v1 = 1.0f - __fdividef(2.0f, e1 + 1.0f);
                            const int hcol = hc0 + nt * 8 + tg * 2;
                            __nv_bfloat16 h0, l0, h1, l1;
                            bf16_split(v0, h0, l0);
                            bf16_split(v1, h1, l1);
                            u32 o = swz(b, hcol);
                            *(__nv_bfloat162*)(smem + O_H_HI + o) = __nv_bfloat162(h0, h1);
                            *(__nv_bfloat162*)(smem + O_H_LO + o) = __nv_bfloat162(l0, l1);
                            if (layer == L - 1 && t == T - 1) {
                                ((float*)(smem + O_HF))[b * H + hcol] = v0;
                                ((float*)(smem + O_HF))[b * H + hcol + 1] = v1;
                            }
                        }
                    }
                __syncthreads();   // S2: sH tile complete

                // copy-out overlaps next step's MMA (both only READ sH;
                // next epilogue's overwrite is fenced by next S1)
                if (layer < L - 1) {
                    uint4* dh = g_hi[wrp] + (u32)(blockIdx.x * T + t) * 512;
                    uint4* dl = g_lo[wrp] + (u32)(blockIdx.x * T + t) * 512;
                    const uint4* shp = (const uint4*)(smem + O_H_HI);
                    const uint4* slp = (const uint4*)(smem + O_H_LO);
                    for (int i = tid; i < 512; i += 256) { dh[i] = shp[i]; dl[i] = slp[i]; }
                }
            }
        }
    }

    // ---- FC on last hidden state ----
    const float* hf = (const float*)(smem + O_HF);
    for (int i = tid; i < BT * C; i += 256) {
        int b = i / C, c = i - b * C;
        float acc = fcb[c];
        const float* w = fcW + c * H;
        const float* hr = hf + b * H;
#pragma unroll 8
        for (int k = 0; k < H; ++k) acc = fmaf(hr[k], w[k], acc);
        out[(bBase + b) * C + c] = acc;
    }
}

extern "C" void kernel_launch(void* const* d_in, const int* in_sizes, int n_in,
                              void* d_out, int out_size) {
    const float* x    = (const float*)d_in[0];
    const float* Wih0 = (const float*)d_in[1];
    const float* Wih  = (const float*)d_in[2];
    const float* Whh  = (const float*)d_in[3];
    const float* bih  = (const float*)d_in[4];
    const float* bhh  = (const float*)d_in[5];
    const float* fcW  = (const float*)d_in[6];
    const float* fcb  = (const float*)d_in[7];
    cudaFuncSetAttribute(rnn_mma, cudaFuncAttributeMaxDynamicSharedMemorySize, SMEM_BYTES);
    rnn_mma<<<NBLK, 256, SMEM_BYTES>>>(x, Wih0, Wih, Whh, bih, bhh, fcW, fcb, (float*)d_out);
}

// round 8
// speedup vs baseline: 2.1642x; 2.1642x over previous
#include <cuda_runtime.h>
#include <cuda_fp16.h>
#include <cstdint>

#define B_TOTAL 4096
#define T 28
#define IN_F 28
#define H 128
#define L 10
#define C 10
#define BT 32
#define NBLK 128   // 4096/32

typedef uint32_t u32;

// Inter-layer activations: verbatim swizzled fp16 tile images (8KB = 512 uint4), ping-pong.
__device__ uint4 g_act[2][NBLK * T * 512];

// ---- SMEM byte offsets ----
#define O_WIH_HI 0
#define O_WIH_LO 32768
#define O_WHH_HI 65536
#define O_WHH_LO 98304
#define O_X0 131072
#define O_X1 139264
#define O_H0 147456
#define O_H1 155648
#define O_HF 163840
#define SMEM_BYTES 180224

static __device__ __forceinline__ u32 smem_u32(const void* p) {
    u32 a;
    asm("{ .reg .u64 t; cvta.to.shared.u64 t, %1; cvt.u32.u64 %0, t; }" : "=r"(a) : "l"(p));
    return a;
}
// XOR-swizzled [row][128 fp16] tile: 16B chunk c of row r lives at chunk (c ^ (r&7)).
static __device__ __forceinline__ u32 swz(int row, int col) {
    return (u32)(row * 256 + ((((col >> 3) ^ (row & 7))) << 4) + (col & 7) * 2);
}
static __device__ __forceinline__ void ldsm4(u32 r[4], u32 a) {
    asm volatile("ldmatrix.sync.aligned.m8n8.x4.shared.b16 {%0,%1,%2,%3}, [%4];"
                 : "=r"(r[0]), "=r"(r[1]), "=r"(r[2]), "=r"(r[3]) : "r"(a));
}
static __device__ __forceinline__ void ldsm2(u32 r[2], u32 a) {
    asm volatile("ldmatrix.sync.aligned.m8n8.x2.shared.b16 {%0,%1}, [%2];"
                 : "=r"(r[0]), "=r"(r[1]) : "r"(a));
}
static __device__ __forceinline__ void mma16816(float c[4], const u32 a[4], const u32 b[2]) {
    asm volatile(
        "mma.sync.aligned.m16n8k16.row.col.f32.f16.f16.f32 "
        "{%0,%1,%2,%3}, {%4,%5,%6,%7}, {%8,%9}, {%0,%1,%2,%3};"
        : "+f"(c[0]), "+f"(c[1]), "+f"(c[2]), "+f"(c[3])
        : "r"(a[0]), "r"(a[1]), "r"(a[2]), "r"(a[3]), "r"(b[0]), "r"(b[1]));
}

__global__ void __launch_bounds__(256, 1)
rnn_mma(const float* __restrict__ x, const float* __restrict__ Wih0,
        const float* __restrict__ Wih, const float* __restrict__ Whh,
        const float* __restrict__ bih, const float* __restrict__ bhh,
        const float* __restrict__ fcW, const float* __restrict__ fcb,
        float* __restrict__ out) {
    extern __shared__ __align__(256) char smem[];
    const u32 sbase = smem_u32(smem);
    const int tid = threadIdx.x;
    const int wid = tid >> 5, lane = tid & 31;
    const int g = lane >> 2, tg = lane & 3;
    const int hc0 = wid * 16;                 // this warp's 16 h-columns
    const int l15 = lane & 15;
    const int arow = lane & 15;
    const int acol = ((lane >> 4) & 1) * 8;
    const int bBase = blockIdx.x * BT;

    // zero X buffers once (layer-0 pad cols 28..127 stay zero)
    {
        uint4 z = make_uint4(0, 0, 0, 0);
        uint4* xb = (uint4*)(smem + O_X0);    // X0+X1 contiguous: 1024 uint4
        for (int i = tid; i < 1024; i += 256) xb[i] = z;
    }
    const int hcol0 = hc0 + tg * 2;
    const int hcol2 = hc0 + 8 + tg * 2;

#pragma unroll 1
    for (int layer = 0; layer < L; ++layer) {
        __threadfence_block();   // publish this CTA's plane STGs for staging reads
        __syncthreads();

        // ---- stage weights (fp16 hi/lo) into swizzled tiles ----
        if (layer == 0) {
            for (int i = tid; i < H * H; i += 256) {
                int m = i >> 7, k = i & 127;
                float w = (k < IN_F) ? Wih0[m * IN_F + k] : 0.0f;
                __half hh = __float2half_rn(w);
                __half ll = __float2half_rn(w - __half2float(hh));
                u32 o = swz(m, k);
                *(__half*)(smem + O_WIH_HI + o) = hh;
                *(__half*)(smem + O_WIH_LO + o) = ll;
            }
        } else {
            const float* Wl = Wih + (layer - 1) * H * H;
            for (int i = tid; i < H * H; i += 256) {
                int m = i >> 7, k = i & 127;
                float w = Wl[i];
                __half hh = __float2half_rn(w);
                __half ll = __float2half_rn(w - __half2float(hh));
                u32 o = swz(m, k);
                *(__half*)(smem + O_WIH_HI + o) = hh;
                *(__half*)(smem + O_WIH_LO + o) = ll;
            }
        }
        {
            const float* Wr = Whh + layer * H * H;
            for (int i = tid; i < H * H; i += 256) {
                int m = i >> 7, k = i & 127;
                float w = Wr[i];
                __half hh = __float2half_rn(w);
                __half ll = __float2half_rn(w - __half2float(hh));
                u32 o = swz(m, k);
                *(__half*)(smem + O_WHH_HI + o) = hh;
                *(__half*)(smem + O_WHH_LO + o) = ll;
            }
        }
        const int rdp = (layer - 1) & 1, wrp = layer & 1;
        float bsum[4];
        bsum[0] = bih[layer * H + hcol0]     + bhh[layer * H + hcol0];
        bsum[1] = bih[layer * H + hcol0 + 1] + bhh[layer * H + hcol0 + 1];
        bsum[2] = bih[layer * H + hcol2]     + bhh[layer * H + hcol2];
        bsum[3] = bih[layer * H + hcol2 + 1] + bhh[layer * H + hcol2 + 1];

        // ---- stage t=0 input ----
        if (layer == 0) {
            for (int i = tid; i < BT * 32; i += 256) {
                int b = i >> 5, k = i & 31;
                if (k < IN_F) {
                    float v = x[((bBase + b) * T + 0) * IN_F + k];
                    *(__half*)(smem + O_X0 + swz(b, k)) = __float2half_rn(v);
                }
            }
        } else {
            const uint4* s = g_act[rdp] + (u32)(blockIdx.x * T) * 512;
            uint4* d = (uint4*)(smem + O_X0);
            for (int i = tid; i < 512; i += 256) d[i] = s[i];
        }
        __syncthreads();

        // ---- load weight fragments (held in registers for all 28 steps) ----
        u32 wih_hi[8][2][2], wih_lo[8][2][2], whh_hi[8][2][2], whh_lo[8][2][2];
#pragma unroll
        for (int kc = 0; kc < 8; ++kc)
#pragma unroll
            for (int nt = 0; nt < 2; ++nt) {
                u32 o = swz(hc0 + nt * 8 + (l15 & 7), kc * 16 + ((l15 >> 3) << 3));
                ldsm2(wih_hi[kc][nt], sbase + O_WIH_HI + o);
                ldsm2(wih_lo[kc][nt], sbase + O_WIH_LO + o);
                ldsm2(whh_hi[kc][nt], sbase + O_WHH_HI + o);
                ldsm2(whh_lo[kc][nt], sbase + O_WHH_LO + o);
            }

#pragma unroll 2
        for (int t = 0; t < T; ++t) {
            const u32 xcur  = sbase + ((t & 1) ? O_X1 : O_X0);
            const u32 hprev = sbase + ((t & 1) ? O_H0 : O_H1);  // written at step t-1

            // ---- stage X[t+1] (overlaps MMA issue; buffer last read at t-1) ----
            if (t + 1 < T) {
                const u32 xn = (t & 1) ? O_X0 : O_X1;
                if (layer == 0) {
                    for (int i = tid; i < BT * 32; i += 256) {
                        int b = i >> 5, k = i & 31;
                        if (k < IN_F) {
                            float v = x[((bBase + b) * T + t + 1) * IN_F + k];
                            *(__half*)(smem + xn + swz(b, k)) = __float2half_rn(v);
                        }
                    }
                } else {
                    const uint4* s = g_act[rdp] + (u32)(blockIdx.x * T + t + 1) * 512;
                    uint4* d = (uint4*)(smem + xn);
                    for (int i = tid; i < 512; i += 256) d[i] = s[i];
                }
            }

            float acc[2][2][4];
#pragma unroll
            for (int mt = 0; mt < 2; ++mt)
#pragma unroll
                for (int nt = 0; nt < 2; ++nt)
#pragma unroll
                    for (int j = 0; j < 4; ++j)
                        acc[mt][nt][j] = bsum[nt * 2 + (j & 1)];

#pragma unroll
            for (int kc = 0; kc < 8; ++kc)
#pragma unroll
                for (int mt = 0; mt < 2; ++mt) {
                    u32 ao = swz(mt * 16 + arow, kc * 16 + acol);
                    u32 ax[4];
                    ldsm4(ax, xcur + ao);
                    if (t > 0) {
                        u32 ah[4];
                        ldsm4(ah, hprev + ao);
#pragma unroll
                        for (int nt = 0; nt < 2; ++nt) {
                            mma16816(acc[mt][nt], ax, wih_hi[kc][nt]);
                            mma16816(acc[mt][nt], ah, whh_hi[kc][nt]);
                            mma16816(acc[mt][nt], ax, wih_lo[kc][nt]);
                            mma16816(acc[mt][nt], ah, whh_lo[kc][nt]);
                        }
                    } else {
#pragma unroll
                        for (int nt = 0; nt < 2; ++nt) {
                            mma16816(acc[mt][nt], ax, wih_hi[kc][nt]);
                            mma16816(acc[mt][nt], ax, wih_lo[kc][nt]);
                        }
                    }
                }

            // ---- epilogue: tanh, write sH ping + plane image directly ----
            const u32 hwr = (t & 1) ? O_H1 : O_H0;
            char* gdst = (char*)(g_act[wrp] + (u32)(blockIdx.x * T + t) * 512);
#pragma unroll
            for (int mt = 0; mt < 2; ++mt)
#pragma unroll
                for (int bs = 0; bs < 2; ++bs) {
                    const int b = mt * 16 + bs * 8 + g;
#pragma unroll
                    for (int nt = 0; nt < 2; ++nt) {
                        float v0 = acc[mt][nt][bs * 2 + 0];
                        float v1 = acc[mt][nt][bs * 2 + 1];
                        float e0 = __expf(2.0f * v0);
                        float e1 = __expf(2.0f * v1);
                        v0 = 1.0f - __fdividef(2.0f, e0 + 1.0f);
                        v1 = 1.0f - __fdividef(2.0f, e1 + 1.0f);
                        const int hcol = hc0 + nt * 8 + tg * 2;
                        __half2 hv;
                        hv.x = __float2half_rn(v0);
                        hv.y = __float2half_rn(v1);
                        u32 o = swz(b, hcol);
                        *(__half2*)(smem + hwr + o) = hv;
                        if (layer < L - 1)
                            *(__half2*)(gdst + o) = hv;
                        if (layer == L - 1 && t == T - 1) {
                            ((float*)(smem + O_HF))[b * H + hcol] = v0;
                            ((float*)(smem + O_HF))[b * H + hcol + 1] = v1;
                        }
                    }
                }
            __syncthreads();   // single barrier: sH[t] + X[t+1] published
        }
    }

    // ---- FC on last hidden state ----
    const float* hf = (const float*)(smem + O_HF);
    for (int i = tid; i < BT * C; i += 256) {
        int b = i / C, c = i - b * C;
        float acc = fcb[c];
        const float* w = fcW + c * H;
        const float* hr = hf + b * H;
#pragma unroll 8
        for (int k = 0; k < H; ++k) acc = fmaf(hr[k], w[k], acc);
        out[(bBase + b) * C + c] = acc;
    }
}

extern "C" void kernel_launch(void* const* d_in, const int* in_sizes, int n_in,
                              void* d_out, int out_size) {
    const float* x    = (const float*)d_in[0];
    const float* Wih0 = (const float*)d_in[1];
    const float* Wih  = (const float*)d_in[2];
    const float* Whh  = (const float*)d_in[3];
    const float* bih  = (const float*)d_in[4];
    const float* bhh  = (const float*)d_in[5];
    const float* fcW  = (const float*)d_in[6];
    const float* fcb  = (const float*)d_in[7];
    cudaFuncSetAttribute(rnn_mma, cudaFuncAttributeMaxDynamicSharedMemorySize, SMEM_BYTES);
    rnn_mma<<<NBLK, 256, SMEM_BYTES>>>(x, Wih0, Wih, Whh, bih, bhh, fcW, fcb, (float*)d_out);
}

// round 11
// speedup vs baseline: 2.4737x; 1.1430x over previous
#include <cuda_runtime.h>
#include <cuda_fp16.h>
#include <cstdint>

#define B_TOTAL 4096
#define T 28
#define IN_F 28
#define H 128
#define L 10
#define C 10
#define BT 32
#define NBLK 128   // 4096/32
#define NTHR 512

typedef uint32_t u32;

// Inter-layer activations: verbatim swizzled fp16 tile images (8KB = 512 uint4), ping-pong.
__device__ uint4 g_act[2][NBLK * T * 512];

// ---- SMEM byte offsets ----
#define O_WIH_HI 0
#define O_WIH_LO 32768
#define O_WHH_HI 65536
#define O_WHH_LO 98304
#define O_X0 131072
#define O_X1 139264
#define O_H0 147456
#define O_H1 155648
#define O_HF 163840
#define SMEM_BYTES 180224

static __device__ __forceinline__ u32 smem_u32(const void* p) {
    u32 a;
    asm("{ .reg .u64 t; cvta.to.shared.u64 t, %1; cvt.u32.u64 %0, t; }" : "=r"(a) : "l"(p));
    return a;
}
// XOR-swizzled [row][128 fp16] tile: 16B chunk c of row r lives at chunk (c ^ (r&7)).
static __device__ __forceinline__ u32 swz(int row, int col) {
    return (u32)(row * 256 + ((((col >> 3) ^ (row & 7))) << 4) + (col & 7) * 2);
}
static __device__ __forceinline__ void ldsm4(u32 r[4], u32 a) {
    asm volatile("ldmatrix.sync.aligned.m8n8.x4.shared.b16 {%0,%1,%2,%3}, [%4];"
                 : "=r"(r[0]), "=r"(r[1]), "=r"(r[2]), "=r"(r[3]) : "r"(a));
}
static __device__ __forceinline__ void ldsm2(u32 r[2], u32 a) {
    asm volatile("ldmatrix.sync.aligned.m8n8.x2.shared.b16 {%0,%1}, [%2];"
                 : "=r"(r[0]), "=r"(r[1]) : "r"(a));
}
static __device__ __forceinline__ void mma16816(float c[4], const u32 a[4], const u32 b[2]) {
    asm volatile(
        "mma.sync.aligned.m16n8k16.row.col.f32.f16.f16.f32 "
        "{%0,%1,%2,%3}, {%4,%5,%6,%7}, {%8,%9}, {%0,%1,%2,%3};"
        : "+f"(c[0]), "+f"(c[1]), "+f"(c[2]), "+f"(c[3])
        : "r"(a[0]), "r"(a[1]), "r"(a[2]), "r"(a[3]), "r"(b[0]), "r"(b[1]));
}
static __device__ __forceinline__ float htanh(float v) {
    float r;
    asm("tanh.approx.f32 %0, %1;" : "=f"(r) : "f"(v));
    return r;
}

__global__ void __launch_bounds__(NTHR, 1)
rnn_mma(const float* __restrict__ x, const float* __restrict__ Wih0,
        const float* __restrict__ Wih, const float* __restrict__ Whh,
        const float* __restrict__ bih, const float* __restrict__ bhh,
        const float* __restrict__ fcW, const float* __restrict__ fcb,
        float* __restrict__ out) {
    extern __shared__ __align__(256) char smem[];
    const u32 sbase = smem_u32(smem);
    const int tid = threadIdx.x;
    const int wid = tid >> 5, lane = tid & 31;
    const int g = lane >> 2, tg = lane & 3;
    const int hc0 = wid * 8;                  // this warp's 8 h-columns
    const int l15 = lane & 15;
    const int arow = lane & 15;
    const int acol = ((lane >> 4) & 1) * 8;
    const int bBase = blockIdx.x * BT;

    // zero X buffers once (layer-0 pad cols 28..127 stay zero)
    {
        uint4 z = make_uint4(0, 0, 0, 0);
        uint4* xb = (uint4*)(smem + O_X0);    // X0+X1 contiguous: 1024 uint4
        for (int i = tid; i < 1024; i += NTHR) xb[i] = z;
    }
    const int hcol0 = hc0 + tg * 2;

#pragma unroll 1
    for (int layer = 0; layer < L; ++layer) {
        __threadfence_block();   // publish this CTA's plane STGs for staging reads
        __syncthreads();

        // ---- stage weights (fp16 hi/lo) into swizzled tiles ----
        if (layer == 0) {
            for (int i = tid; i < H * H; i += NTHR) {
                int m = i >> 7, k = i & 127;
                float w = (k < IN_F) ? Wih0[m * IN_F + k] : 0.0f;
                __half hh = __float2half_rn(w);
                __half ll = __float2half_rn(w - __half2float(hh));
                u32 o = swz(m, k);
                *(__half*)(smem + O_WIH_HI + o) = hh;
                *(__half*)(smem + O_WIH_LO + o) = ll;
            }
        } else {
            const float* Wl = Wih + (layer - 1) * H * H;
            for (int i = tid; i < H * H; i += NTHR) {
                int m = i >> 7, k = i & 127;
                float w = Wl[i];
                __half hh = __float2half_rn(w);
                __half ll = __float2half_rn(w - __half2float(hh));
                u32 o = swz(m, k);
                *(__half*)(smem + O_WIH_HI + o) = hh;
                *(__half*)(smem + O_WIH_LO + o) = ll;
            }
        }
        {
            const float* Wr = Whh + layer * H * H;
            for (int i = tid; i < H * H; i += NTHR) {
                int m = i >> 7, k = i & 127;
                float w = Wr[i];
                __half hh = __float2half_rn(w);
                __half ll = __float2half_rn(w - __half2float(hh));
                u32 o = swz(m, k);
                *(__half*)(smem + O_WHH_HI + o) = hh;
                *(__half*)(smem + O_WHH_LO + o) = ll;
            }
        }
        const int rdp = (layer - 1) & 1, wrp = layer & 1;
        float bs0 = bih[layer * H + hcol0]     + bhh[layer * H + hcol0];
        float bs1 = bih[layer * H + hcol0 + 1] + bhh[layer * H + hcol0 + 1];

        // ---- stage t=0 input ----
        if (layer == 0) {
            for (int i = tid; i < BT * 32; i += NTHR) {
                int b = i >> 5, k = i & 31;
                if (k < IN_F) {
                    float v = x[((bBase + b) * T + 0) * IN_F + k];
                    *(__half*)(smem + O_X0 + swz(b, k)) = __float2half_rn(v);
                }
            }
        } else {
            const uint4* s = g_act[rdp] + (u32)(blockIdx.x * T) * 512;
            uint4* d = (uint4*)(smem + O_X0);
            for (int i = tid; i < 512; i += NTHR) d[i] = s[i];
        }
        __syncthreads();

        // ---- load weight fragments (held in registers for all 28 steps) ----
        u32 wih_hi[8][2], wih_lo[8][2], whh_hi[8][2], whh_lo[8][2];
#pragma unroll
        for (int kc = 0; kc < 8; ++kc) {
            u32 o = swz(hc0 + (l15 & 7), kc * 16 + ((l15 >> 3) << 3));
            ldsm2(wih_hi[kc], sbase + O_WIH_HI + o);
            ldsm2(wih_lo[kc], sbase + O_WIH_LO + o);
            ldsm2(whh_hi[kc], sbase + O_WHH_HI + o);
            ldsm2(whh_lo[kc], sbase + O_WHH_LO + o);
        }

#pragma unroll 2
        for (int t = 0; t < T; ++t) {
            const u32 xcur  = sbase + ((t & 1) ? O_X1 : O_X0);
            const u32 hprev = sbase + ((t & 1) ? O_H0 : O_H1);  // written at step t-1

            // ---- stage X[t+1] (overlaps MMA issue; buffer last read at t-1) ----
            if (t + 1 < T) {
                const u32 xn = (t & 1) ? O_X0 : O_X1;
                if (layer == 0) {
                    for (int i = tid; i < BT * 32; i += NTHR) {
                        int b = i >> 5, k = i & 31;
                        if (k < IN_F) {
                            float v = x[((bBase + b) * T + t + 1) * IN_F + k];
                            *(__half*)(smem + xn + swz(b, k)) = __float2half_rn(v);
                        }
                    }
                } else {
                    const uint4* s = g_act[rdp] + (u32)(blockIdx.x * T + t + 1) * 512;
                    uint4* d = (uint4*)(smem + xn);
                    for (int i = tid; i < 512; i += NTHR) d[i] = s[i];
                }
            }

            float acc[2][4];
#pragma unroll
            for (int mt = 0; mt < 2; ++mt) {
                acc[mt][0] = bs0; acc[mt][1] = bs1;
                acc[mt][2] = bs0; acc[mt][3] = bs1;
            }

#pragma unroll
            for (int kc = 0; kc < 8; ++kc)
#pragma unroll
                for (int mt = 0; mt < 2; ++mt) {
                    u32 ao = swz(mt * 16 + arow, kc * 16 + acol);
                    u32 ax[4];
                    ldsm4(ax, xcur + ao);
                    if (t > 0) {
                        u32 ah[4];
                        ldsm4(ah, hprev + ao);
                        mma16816(acc[mt], ax, wih_hi[kc]);
                        mma16816(acc[mt], ah, whh_hi[kc]);
                        mma16816(acc[mt], ax, wih_lo[kc]);
                        mma16816(acc[mt], ah, whh_lo[kc]);
                    } else {
                        mma16816(acc[mt], ax, wih_hi[kc]);
                        mma16816(acc[mt], ax, wih_lo[kc]);
                    }
                }

            // ---- epilogue: HW tanh, write sH ping + plane image directly ----
            const u32 hwr = (t & 1) ? O_H1 : O_H0;
            char* gdst = (char*)(g_act[wrp] + (u32)(blockIdx.x * T + t) * 512);
#pragma unroll
            for (int mt = 0; mt < 2; ++mt)
#pragma unroll
                for (int bs = 0; bs < 2; ++bs) {
                    const int b = mt * 16 + bs * 8 + g;
                    float v0 = htanh(acc[mt][bs * 2 + 0]);
                    float v1 = htanh(acc[mt][bs * 2 + 1]);
                    __half2 hv;
                    hv.x = __float2half_rn(v0);
                    hv.y = __float2half_rn(v1);
                    u32 o = swz(b, hcol0);
                    *(__half2*)(smem + hwr + o) = hv;
                    if (layer < L - 1)
                        *(__half2*)(gdst + o) = hv;
                    if (layer == L - 1 && t == T - 1) {
                        ((float*)(smem + O_HF))[b * H + hcol0] = v0;
                        ((float*)(smem + O_HF))[b * H + hcol0 + 1] = v1;
                    }
                }
            __syncthreads();   // single barrier: sH[t] + X[t+1] published
        }
    }

    // ---- FC on last hidden state ----
    const float* hf = (const float*)(smem + O_HF);
    for (int i = tid; i < BT * C; i += NTHR) {
        int b = i / C, c = i - b * C;
        float acc = fcb[c];
        const float* w = fcW + c * H;
        const float* hr = hf + b * H;
#pragma unroll 8
        for (int k = 0; k < H; ++k) acc = fmaf(hr[k], w[k], acc);
        out[(bBase + b) * C + c] = acc;
    }
}

extern "C" void kernel_launch(void* const* d_in, const int* in_sizes, int n_in,
                              void* d_out, int out_size) {
    const float* x    = (const float*)d_in[0];
    const float* Wih0 = (const float*)d_in[1];
    const float* Wih  = (const float*)d_in[2];
    const float* Whh  = (const float*)d_in[3];
    const float* bih  = (const float*)d_in[4];
    const float* bhh  = (const float*)d_in[5];
    const float* fcW  = (const float*)d_in[6];
    const float* fcb  = (const float*)d_in[7];
    cudaFuncSetAttribute(rnn_mma, cudaFuncAttributeMaxDynamicSharedMemorySize, SMEM_BYTES);
    rnn_mma<<<NBLK, NTHR, SMEM_BYTES>>>(x, Wih0, Wih, Whh, bih, bhh, fcW, fcb, (float*)d_out);
}

// round 12
// speedup vs baseline: 2.9327x; 1.1856x over previous
#include <cuda_runtime.h>
#include <cuda_fp16.h>
#include <cstdint>

#define B_TOTAL 4096
#define T 28
#define IN_F 28
#define H 128
#define L 10
#define C 10
#define BT 32
#define NBLK 128   // 4096/32
#define NTHR 512

typedef uint32_t u32;

// Inter-layer activations: verbatim swizzled fp16 tile images (8KB = 512 uint4), ping-pong.
__device__ uint4 g_act[2][NBLK * T * 512];

// ---- SMEM byte offsets ----
#define O_WIH 0
#define O_WHH 32768
#define O_X0  65536
#define O_X1  73728
#define O_H0  81920
#define O_H1  90112
#define O_HF  98304
#define SMEM_BYTES 114688

static __device__ __forceinline__ u32 smem_u32(const void* p) {
    u32 a;
    asm("{ .reg .u64 t; cvta.to.shared.u64 t, %1; cvt.u32.u64 %0, t; }" : "=r"(a) : "l"(p));
    return a;
}
// XOR-swizzled [row][128 fp16] tile: 16B chunk c of row r lives at chunk (c ^ (r&7)).
static __device__ __forceinline__ u32 swz(int row, int col) {
    return (u32)(row * 256 + ((((col >> 3) ^ (row & 7))) << 4) + (col & 7) * 2);
}
static __device__ __forceinline__ void ldsm4(u32 r[4], u32 a) {
    asm volatile("ldmatrix.sync.aligned.m8n8.x4.shared.b16 {%0,%1,%2,%3}, [%4];"
                 : "=r"(r[0]), "=r"(r[1]), "=r"(r[2]), "=r"(r[3]) : "r"(a));
}
static __device__ __forceinline__ void ldsm2(u32 r[2], u32 a) {
    asm volatile("ldmatrix.sync.aligned.m8n8.x2.shared.b16 {%0,%1}, [%2];"
                 : "=r"(r[0]), "=r"(r[1]) : "r"(a));
}
static __device__ __forceinline__ void mma16816(float c[4], const u32 a[4], const u32 b[2]) {
    asm volatile(
        "mma.sync.aligned.m16n8k16.row.col.f32.f16.f16.f32 "
        "{%0,%1,%2,%3}, {%4,%5,%6,%7}, {%8,%9}, {%0,%1,%2,%3};"
        : "+f"(c[0]), "+f"(c[1]), "+f"(c[2]), "+f"(c[3])
        : "r"(a[0]), "r"(a[1]), "r"(a[2]), "r"(a[3]), "r"(b[0]), "r"(b[1]));
}
static __device__ __forceinline__ float htanh(float v) {
    float r;
    asm("tanh.approx.f32 %0, %1;" : "=f"(r) : "f"(v));
    return r;
}

__global__ void __launch_bounds__(NTHR, 1)
rnn_mma(const float* __restrict__ x, const float* __restrict__ Wih0,
        const float* __restrict__ Wih, const float* __restrict__ Whh,
        const float* __restrict__ bih, const float* __restrict__ bhh,
        const float* __restrict__ fcW, const float* __restrict__ fcb,
        float* __restrict__ out) {
    extern __shared__ __align__(256) char smem[];
    const u32 sbase = smem_u32(smem);
    const int tid = threadIdx.x;
    const int wid = tid >> 5, lane = tid & 31;
    const int g = lane >> 2, tg = lane & 3;
    const int hc0 = wid * 8;                  // this warp's 8 h-columns
    const int l15 = lane & 15;
    const int arow = lane & 15;
    const int acol = ((lane >> 4) & 1) * 8;
    const int bBase = blockIdx.x * BT;

    // zero X buffers once (layer-0 pad cols 28..31 stay zero)
    {
        uint4 z = make_uint4(0, 0, 0, 0);
        uint4* xb = (uint4*)(smem + O_X0);    // X0+X1 contiguous: 1024 uint4
        for (int i = tid; i < 1024; i += NTHR) xb[i] = z;
    }
    const int hcol0 = hc0 + tg * 2;

#pragma unroll 1
    for (int layer = 0; layer < L; ++layer) {
        __threadfence_block();   // publish this CTA's plane STGs for staging reads
        __syncthreads();

        // ---- stage weights (fp16) into swizzled tiles ----
        if (layer == 0) {
            for (int i = tid; i < H * 32; i += NTHR) {
                int m = i >> 5, k = i & 31;
                float w = (k < IN_F) ? Wih0[m * IN_F + k] : 0.0f;
                *(__half*)(smem + O_WIH + swz(m, k)) = __float2half_rn(w);
            }
        } else {
            const float* Wl = Wih + (layer - 1) * H * H;
            for (int i = tid; i < H * H; i += NTHR) {
                int m = i >> 7, k = i & 127;
                *(__half*)(smem + O_WIH + swz(m, k)) = __float2half_rn(Wl[i]);
            }
        }
        {
            const float* Wr = Whh + layer * H * H;
            for (int i = tid; i < H * H; i += NTHR) {
                int m = i >> 7, k = i & 127;
                *(__half*)(smem + O_WHH + swz(m, k)) = __float2half_rn(Wr[i]);
            }
        }
        const int rdp = (layer - 1) & 1, wrp = layer & 1;
        const int nkx = (layer == 0) ? 2 : 8;   // x-projection K chunks
        float bs0 = bih[layer * H + hcol0]     + bhh[layer * H + hcol0];
        float bs1 = bih[layer * H + hcol0 + 1] + bhh[layer * H + hcol0 + 1];

        // ---- stage t=0 input ----
        if (layer == 0) {
            for (int i = tid; i < BT * 32; i += NTHR) {
                int b = i >> 5, k = i & 31;
                if (k < IN_F) {
                    float v = x[((bBase + b) * T + 0) * IN_F + k];
                    *(__half*)(smem + O_X0 + swz(b, k)) = __float2half_rn(v);
                }
            }
        } else {
            const uint4* s = g_act[rdp] + (u32)(blockIdx.x * T) * 512;
            uint4* d = (uint4*)(smem + O_X0);
            for (int i = tid; i < 512; i += NTHR) d[i] = s[i];
        }
        __syncthreads();

        // ---- load weight fragments (held in registers for all 28 steps) ----
        u32 wih[8][2], whh[8][2];
#pragma unroll
        for (int kc = 0; kc < 8; ++kc) {
            u32 o = swz(hc0 + (l15 & 7), kc * 16 + ((l15 >> 3) << 3));
            ldsm2(wih[kc], sbase + O_WIH + o);
            ldsm2(whh[kc], sbase + O_WHH + o);
        }

#pragma unroll 2
        for (int t = 0; t < T; ++t) {
            const u32 xcur  = sbase + ((t & 1) ? O_X1 : O_X0);
            const u32 hprev = sbase + ((t & 1) ? O_H0 : O_H1);  // written at step t-1

            float acc[2][4];
#pragma unroll
            for (int mt = 0; mt < 2; ++mt) {
                acc[mt][0] = bs0; acc[mt][1] = bs1;
                acc[mt][2] = bs0; acc[mt][3] = bs1;
            }

            // ---- MMA: input projection (nkx chunks) + recurrent (8 chunks) ----
#pragma unroll
            for (int kc = 0; kc < 8; ++kc)
#pragma unroll
                for (int mt = 0; mt < 2; ++mt) {
                    u32 ao = swz(mt * 16 + arow, kc * 16 + acol);
                    if (kc < nkx) {
                        u32 ax[4];
                        ldsm4(ax, xcur + ao);
                        mma16816(acc[mt], ax, wih[kc]);
                    }
                    if (t > 0) {
                        u32 ah[4];
                        ldsm4(ah, hprev + ao);
                        mma16816(acc[mt], ah, whh[kc]);
                    }
                }

            // ---- stage X[t+1]: LDG latency hides under HMMA drain ----
            if (t + 1 < T) {
                const u32 xn = (t & 1) ? O_X0 : O_X1;
                if (layer == 0) {
                    for (int i = tid; i < BT * 32; i += NTHR) {
                        int b = i >> 5, k = i & 31;
                        if (k < IN_F) {
                            float v = x[((bBase + b) * T + t + 1) * IN_F + k];
                            *(__half*)(smem + xn + swz(b, k)) = __float2half_rn(v);
                        }
                    }
                } else {
                    const uint4* s = g_act[rdp] + (u32)(blockIdx.x * T + t + 1) * 512;
                    uint4* d = (uint4*)(smem + xn);
                    for (int i = tid; i < 512; i += NTHR) d[i] = s[i];
                }
            }

            // ---- epilogue: HW tanh, write sH ping + plane image directly ----
            const u32 hwr = (t & 1) ? O_H1 : O_H0;
            char* gdst = (char*)(g_act[wrp] + (u32)(blockIdx.x * T + t) * 512);
#pragma unroll
            for (int mt = 0; mt < 2; ++mt)
#pragma unroll
                for (int bs = 0; bs < 2; ++bs) {
                    const int b = mt * 16 + bs * 8 + g;
                    float v0 = htanh(acc[mt][bs * 2 + 0]);
                    float v1 = htanh(acc[mt][bs * 2 + 1]);
                    __half2 hv;
                    hv.x = __float2half_rn(v0);
                    hv.y = __float2half_rn(v1);
                    u32 o = swz(b, hcol0);
                    *(__half2*)(smem + hwr + o) = hv;
                    if (layer < L - 1)
                        *(__half2*)(gdst + o) = hv;
                    if (layer == L - 1 && t == T - 1) {
                        ((float*)(smem + O_HF))[b * H + hcol0] = v0;
                        ((float*)(smem + O_HF))[b * H + hcol0 + 1] = v1;
                    }
                }
            __syncthreads();   // single barrier: sH[t] + X[t+1] published
        }
    }

    // ---- FC on last hidden state ----
    const float* hf = (const float*)(smem + O_HF);
    for (int i = tid; i < BT * C; i += NTHR) {
        int b = i / C, c = i - b * C;
        float acc = fcb[c];
        const float* w = fcW + c * H;
        const float* hr = hf + b * H;
#pragma unroll 8
        for (int k = 0; k < H; ++k) acc = fmaf(hr[k], w[k], acc);
        out[(bBase + b) * C + c] = acc;
    }
}

extern "C" void kernel_launch(void* const* d_in, const int* in_sizes, int n_in,
                              void* d_out, int out_size) {
    const float* x    = (const float*)d_in[0];
    const float* Wih0 = (const float*)d_in[1];
    const float* Wih  = (const float*)d_in[2];
    const float* Whh  = (const float*)d_in[3];
    const float* bih  = (const float*)d_in[4];
    const float* bhh  = (const float*)d_in[5];
    const float* fcW  = (const float*)d_in[6];
    const float* fcb  = (const float*)d_in[7];
    cudaFuncSetAttribute(rnn_mma, cudaFuncAttributeMaxDynamicSharedMemorySize, SMEM_BYTES);
    rnn_mma<<<NBLK, NTHR, SMEM_BYTES>>>(x, Wih0, Wih, Whh, bih, bhh, fcW, fcb, (float*)d_out);
}

// round 13
// speedup vs baseline: 3.5898x; 1.2241x over previous
#include <cuda_runtime.h>
#include <cuda_fp16.h>
#include <cstdint>

#define B_TOTAL 4096
#define T 28
#define IN_F 28
#define H 128
#define L 10
#define C 10
#define BT 32
#define NBLK 128   // 4096/32
#define NTHR 512

typedef uint32_t u32;

// Inter-layer activations: verbatim swizzled fp16 tile images (8KB = 512 uint4), ping-pong.
__device__ uint4 g_act[2][NBLK * T * 512];

// ---- SMEM byte offsets ----
#define O_WIH 0
#define O_WHH 32768
#define O_X0  65536
#define O_X1  73728
#define O_H0  81920
#define O_H1  90112
#define O_HF  98304
#define SMEM_BYTES 114688

static __device__ __forceinline__ u32 smem_u32(const void* p) {
    u32 a;
    asm("{ .reg .u64 t; cvta.to.shared.u64 t, %1; cvt.u32.u64 %0, t; }" : "=r"(a) : "l"(p));
    return a;
}
// XOR-swizzled [row][128 fp16] tile: 16B chunk c of row r lives at chunk (c ^ (r&7)).
static __device__ __forceinline__ u32 swz(int row, int col) {
    return (u32)(row * 256 + ((((col >> 3) ^ (row & 7))) << 4) + (col & 7) * 2);
}
static __device__ __forceinline__ void ldsm4(u32 r[4], u32 a) {
    asm volatile("ldmatrix.sync.aligned.m8n8.x4.shared.b16 {%0,%1,%2,%3}, [%4];"
                 : "=r"(r[0]), "=r"(r[1]), "=r"(r[2]), "=r"(r[3]) : "r"(a));
}
static __device__ __forceinline__ void ldsm2(u32 r[2], u32 a) {
    asm volatile("ldmatrix.sync.aligned.m8n8.x2.shared.b16 {%0,%1}, [%2];"
                 : "=r"(r[0]), "=r"(r[1]) : "r"(a));
}
static __device__ __forceinline__ void mma16816(float c[4], const u32 a[4], const u32 b[2]) {
    asm volatile(
        "mma.sync.aligned.m16n8k16.row.col.f32.f16.f16.f32 "
        "{%0,%1,%2,%3}, {%4,%5,%6,%7}, {%8,%9}, {%0,%1,%2,%3};"
        : "+f"(c[0]), "+f"(c[1]), "+f"(c[2]), "+f"(c[3])
        : "r"(a[0]), "r"(a[1]), "r"(a[2]), "r"(a[3]), "r"(b[0]), "r"(b[1]));
}
static __device__ __forceinline__ float htanh(float v) {
    float r;
    asm("tanh.approx.f32 %0, %1;" : "=f"(r) : "f"(v));
    return r;
}
static __device__ __forceinline__ void barh(int id) {
    asm volatile("bar.sync %0, %1;" :: "r"(id), "r"(256) : "memory");
}

__global__ void __launch_bounds__(NTHR, 1)
rnn_mma(const float* __restrict__ x, const float* __restrict__ Wih0,
        const float* __restrict__ Wih, const float* __restrict__ Whh,
        const float* __restrict__ bih, const float* __restrict__ bhh,
        const float* __restrict__ fcW, const float* __restrict__ fcb,
        float* __restrict__ out) {
    extern __shared__ __align__(256) char smem[];
    const u32 sbase = smem_u32(smem);
    const int tid = threadIdx.x;
    const int wid = tid >> 5, lane = tid & 31;
    const int g = lane >> 2, tg = lane & 3;
    const int half = wid >> 3;                // 0: rows 0-15, 1: rows 16-31
    const int w8 = wid & 7;
    const int hc0 = w8 * 16;                  // this warp's 16 h-columns
    const int brow0 = half * 16;              // this half's batch-row base
    const int barid = 1 + half;
    const int tid256 = tid & 255;             // thread id within half
    const int l15 = lane & 15;
    const int arow = lane & 15;
    const int acol = ((lane >> 4) & 1) * 8;
    const int bBase = blockIdx.x * BT;

    // zero X buffers once (layer-0 pad cols 28..31 stay zero)
    {
        uint4 z = make_uint4(0, 0, 0, 0);
        uint4* xb = (uint4*)(smem + O_X0);    // X0+X1 contiguous: 1024 uint4
        for (int i = tid; i < 1024; i += NTHR) xb[i] = z;
    }
    const int hcol0 = hc0 + tg * 2;           // first of this thread's h-col pairs

#pragma unroll 1
    for (int layer = 0; layer < L; ++layer) {
        __syncthreads();   // rejoin halves; prev layer fully done

        // ---- stage weights (fp16) into swizzled tiles (full block) ----
        if (layer == 0) {
            for (int i = tid; i < H * 32; i += NTHR) {
                int m = i >> 5, k = i & 31;
                float w = (k < IN_F) ? Wih0[m * IN_F + k] : 0.0f;
                *(__half*)(smem + O_WIH + swz(m, k)) = __float2half_rn(w);
            }
        } else {
            const float* Wl = Wih + (layer - 1) * H * H;
            for (int i = tid; i < H * H; i += NTHR) {
                int m = i >> 7, k = i & 127;
                *(__half*)(smem + O_WIH + swz(m, k)) = __float2half_rn(Wl[i]);
            }
        }
        {
            const float* Wr = Whh + layer * H * H;
            for (int i = tid; i < H * H; i += NTHR) {
                int m = i >> 7, k = i & 127;
                *(__half*)(smem + O_WHH + swz(m, k)) = __float2half_rn(Wr[i]);
            }
        }
        const int rdp = (layer - 1) & 1, wrp = layer & 1;
        const int nkx = (layer == 0) ? 2 : 8;   // x-projection K chunks

        float bs0[2], bs1[2];
#pragma unroll
        for (int nt = 0; nt < 2; ++nt) {
            bs0[nt] = bih[layer * H + hcol0 + nt * 8] + bhh[layer * H + hcol0 + nt * 8];
            bs1[nt] = bih[layer * H + hcol0 + nt * 8 + 1] + bhh[layer * H + hcol0 + nt * 8 + 1];
        }

        // ---- stage t=0 input (full block) ----
        if (layer == 0) {
            for (int i = tid; i < BT * 32; i += NTHR) {
                int b = i >> 5, k = i & 31;
                if (k < IN_F) {
                    float v = x[((bBase + b) * T + 0) * IN_F + k];
                    *(__half*)(smem + O_X0 + swz(b, k)) = __float2half_rn(v);
                }
            }
        } else {
            const uint4* s = g_act[rdp] + (u32)(blockIdx.x * T) * 512;
            uint4* d = (uint4*)(smem + O_X0);
            for (int i = tid; i < 512; i += NTHR) d[i] = s[i];
        }
        __syncthreads();

        // ---- load weight fragments (held in registers for all 28 steps) ----
        u32 wih[8][2][2], whh[8][2][2];
#pragma unroll
        for (int kc = 0; kc < 8; ++kc)
#pragma unroll
            for (int nt = 0; nt < 2; ++nt) {
                u32 o = swz(hc0 + nt * 8 + (l15 & 7), kc * 16 + ((l15 >> 3) << 3));
                ldsm2(wih[kc][nt], sbase + O_WIH + o);
                ldsm2(whh[kc][nt], sbase + O_WHH + o);
            }

        // ======== per-half asynchronous recurrence ========
#pragma unroll 1
        for (int t = 0; t < T; ++t) {
            const u32 xcur  = sbase + ((t & 1) ? O_X1 : O_X0);
            const u32 hprev = sbase + ((t & 1) ? O_H0 : O_H1);

            // 4 split-K accumulator sets -> dependent chains of depth <= 4
            float axa[2][4], axb[2][4], aha[2][4], ahb[2][4];
#pragma unroll
            for (int nt = 0; nt < 2; ++nt)
#pragma unroll
                for (int j = 0; j < 4; ++j) {
                    axa[nt][j] = (j & 1) ? bs1[nt] : bs0[nt];
                    axb[nt][j] = 0.0f; aha[nt][j] = 0.0f; ahb[nt][j] = 0.0f;
                }

            // recurrent part first (critical path)
            if (t > 0) {
#pragma unroll
                for (int kc = 0; kc < 8; ++kc) {
                    u32 ah[4];
                    ldsm4(ah, hprev + swz(brow0 + arow, kc * 16 + acol));
                    float (*dst)[4] = (kc < 4) ? aha : ahb;
                    mma16816(dst[0], ah, whh[kc][0]);
                    mma16816(dst[1], ah, whh[kc][1]);
                }
            }
            // input projection (off critical path, fills issue slots)
#pragma unroll
            for (int kc = 0; kc < 8; ++kc) {
                if (kc < nkx) {
                    u32 ax[4];
                    ldsm4(ax, xcur + swz(brow0 + arow, kc * 16 + acol));
                    float (*dst)[4] = (kc < 4) ? axa : axb;
                    mma16816(dst[0], ax, wih[kc][0]);
                    mma16816(dst[1], ax, wih[kc][1]);
                }
            }

            // ---- stage this half's rows of X[t+1] (hides LDG under MMA drain) ----
            if (t + 1 < T) {
                const u32 xn = (t & 1) ? O_X0 : O_X1;
                if (layer == 0) {
                    for (int i = tid256; i < 512; i += 256) {
                        int b = brow0 + (i >> 5), k = i & 31;
                        if (k < IN_F) {
                            float v = x[((bBase + b) * T + t + 1) * IN_F + k];
                            *(__half*)(smem + xn + swz(b, k)) = __float2half_rn(v);
                        }
                    }
                } else {
                    const uint4* s = g_act[rdp] + (u32)(blockIdx.x * T + t + 1) * 512 + brow0 * 16;
                    uint4* d = (uint4*)(smem + xn) + brow0 * 16;
                    d[tid256] = s[tid256];
                }
            }

            // ---- merge, tanh, write sH ping + plane image directly ----
            const u32 hwr = (t & 1) ? O_H1 : O_H0;
            char* gdst = (char*)(g_act[wrp] + (u32)(blockIdx.x * T + t) * 512);
#pragma unroll
            for (int nt = 0; nt < 2; ++nt)
#pragma unroll
                for (int bs = 0; bs < 2; ++bs) {
                    const int b = brow0 + bs * 8 + g;
                    float v0 = htanh((axa[nt][bs * 2 + 0] + axb[nt][bs * 2 + 0])
                                   + (aha[nt][bs * 2 + 0] + ahb[nt][bs * 2 + 0]));
                    float v1 = htanh((axa[nt][bs * 2 + 1] + axb[nt][bs * 2 + 1])
                                   + (aha[nt][bs * 2 + 1] + ahb[nt][bs * 2 + 1]));
                    __half2 hv;
                    hv.x = __float2half_rn(v0);
                    hv.y = __float2half_rn(v1);
                    const int hcol = hc0 + nt * 8 + tg * 2;
                    u32 o = swz(b, hcol);
                    *(__half2*)(smem + hwr + o) = hv;
                    if (layer < L - 1)
                        *(__half2*)(gdst + o) = hv;
                    if (layer == L - 1 && t == T - 1) {
                        ((float*)(smem + O_HF))[b * H + hcol] = v0;
                        ((float*)(smem + O_HF))[b * H + hcol + 1] = v1;
                    }
                }
            barh(barid);   // per-half barrier: sH[t] + X[t+1] published
        }
    }

    __syncthreads();   // both halves' O_HF writes visible

    // ---- FC on last hidden state ----
    const float* hf = (const float*)(smem + O_HF);
    for (int i = tid; i < BT * C; i += NTHR) {
        int b = i / C, c = i - b * C;
        float acc = fcb[c];
        const float* w = fcW + c * H;
        const float* hr = hf + b * H;
#pragma unroll 8
        for (int k = 0; k < H; ++k) acc = fmaf(hr[k], w[k], acc);
        out[(bBase + b) * C + c] = acc;
    }
}

extern "C" void kernel_launch(void* const* d_in, const int* in_sizes, int n_in,
                              void* d_out, int out_size) {
    const float* x    = (const float*)d_in[0];
    const float* Wih0 = (const float*)d_in[1];
    const float* Wih  = (const float*)d_in[2];
    const float* Whh  = (const float*)d_in[3];
    const float* bih  = (const float*)d_in[4];
    const float* bhh  = (const float*)d_in[5];
    const float* fcW  = (const float*)d_in[6];
    const float* fcb  = (const float*)d_in[7];
    cudaFuncSetAttribute(rnn_mma, cudaFuncAttributeMaxDynamicSharedMemorySize, SMEM_BYTES);
    rnn_mma<<<NBLK, NTHR, SMEM_BYTES>>>(x, Wih0, Wih, Whh, bih, bhh, fcW, fcb, (float*)d_out);
}

// round 16
// speedup vs baseline: 4.4534x; 1.2405x over previous
#include <cuda_runtime.h>
#include <cuda_fp16.h>
#include <cstdint>

#define B_TOTAL 4096
#define T 28
#define IN_F 28
#define H 128
#define L 10
#define C 10
#define BT 32
#define NBLK 128   // 4096/32
#define NTHR 512

typedef uint32_t u32;

// Inter-layer activations: verbatim swizzled fp16 tile images (8KB = 512 uint4), ping-pong.
__device__ uint4 g_act[2][NBLK * T * 512];

// ---- SMEM byte offsets ----
#define O_WIH 0
#define O_WHH 32768
#define O_XR  65536          // X ring: 3 x 8192
#define O_H0  90112
#define O_H1  98304
#define O_HF  106496
#define SMEM_BYTES 122880

static __device__ __forceinline__ u32 smem_u32(const void* p) {
    u32 a;
    asm("{ .reg .u64 t; cvta.to.shared.u64 t, %1; cvt.u32.u64 %0, t; }" : "=r"(a) : "l"(p));
    return a;
}
// XOR-swizzled [row][128 fp16] tile: 16B chunk c of row r lives at chunk (c ^ (r&7)).
static __device__ __forceinline__ u32 swz(int row, int col) {
    return (u32)(row * 256 + ((((col >> 3) ^ (row & 7))) << 4) + (col & 7) * 2);
}
static __device__ __forceinline__ void ldsm4(u32 r[4], u32 a) {
    asm volatile("ldmatrix.sync.aligned.m8n8.x4.shared.b16 {%0,%1,%2,%3}, [%4];"
                 : "=r"(r[0]), "=r"(r[1]), "=r"(r[2]), "=r"(r[3]) : "r"(a));
}
static __device__ __forceinline__ void ldsm2(u32 r[2], u32 a) {
    asm volatile("ldmatrix.sync.aligned.m8n8.x2.shared.b16 {%0,%1}, [%2];"
                 : "=r"(r[0]), "=r"(r[1]) : "r"(a));
}
static __device__ __forceinline__ void mma16816(float c[4], const u32 a[4], const u32 b[2]) {
    asm volatile(
        "mma.sync.aligned.m16n8k16.row.col.f32.f16.f16.f32 "
        "{%0,%1,%2,%3}, {%4,%5,%6,%7}, {%8,%9}, {%0,%1,%2,%3};"
        : "+f"(c[0]), "+f"(c[1]), "+f"(c[2]), "+f"(c[3])
        : "r"(a[0]), "r"(a[1]), "r"(a[2]), "r"(a[3]), "r"(b[0]), "r"(b[1]));
}
static __device__ __forceinline__ float htanh(float v) {
    float r;
    asm("tanh.approx.f32 %0, %1;" : "=f"(r) : "f"(v));
    return r;
}
// pack two f32 into half2 bits
static __device__ __forceinline__ u32 pack_h2(float v0, float v1) {
    u32 p;
    asm("cvt.rn.f16x2.f32 %0, %1, %2;" : "=r"(p) : "f"(v1), "f"(v0));
    return p;
}
static __device__ __forceinline__ void barh(int id) {
    asm volatile("bar.sync %0, %1;" :: "r"(id), "r"(256) : "memory");
}
#define CP_ASYNC16(dst, src) \
    asm volatile("cp.async.cg.shared.global [%0], [%1], 16;" :: "r"(dst), "l"(src))
#define CP_COMMIT() asm volatile("cp.async.commit_group;" ::: "memory")
#define CP_WAIT0()  asm volatile("cp.async.wait_group 0;" ::: "memory")

__global__ void __launch_bounds__(NTHR, 1)
rnn_mma(const float* __restrict__ x, const float* __restrict__ Wih0,
        const float* __restrict__ Wih, const float* __restrict__ Whh,
        const float* __restrict__ bih, const float* __restrict__ bhh,
        const float* __restrict__ fcW, const float* __restrict__ fcb,
        float* __restrict__ out) {
    extern __shared__ __align__(256) char smem[];
    const u32 sbase = smem_u32(smem);
    const int tid = threadIdx.x;
    const int wid = tid >> 5, lane = tid & 31;
    const int g = lane >> 2, tg = lane & 3;
    const int half = wid >> 3;                // 0: rows 0-15, 1: rows 16-31
    const int w8 = wid & 7;
    const int hc0 = w8 * 16;                  // this warp's 16 h-columns
    const int brow0 = half * 16;
    const int barid = 1 + half;
    const int tid256 = tid & 255;
    const int l15 = lane & 15;
    const int arow = lane & 15;
    const int acol = ((lane >> 4) & 1) * 8;
    const int bBase = blockIdx.x * BT;

    // per-thread constant offsets
    u32 aoff[8];
#pragma unroll
    for (int kc = 0; kc < 8; ++kc)
        aoff[kc] = swz(brow0 + arow, kc * 16 + acol);
    u32 eoff[2][2];
#pragma unroll
    for (int nt = 0; nt < 2; ++nt)
#pragma unroll
        for (int bs = 0; bs < 2; ++bs)
            eoff[nt][bs] = swz(brow0 + bs * 8 + g, hc0 + nt * 8 + tg * 2);

    // zero X ring once (layer-0 pad cols stay zero; layers>0 overwrite fully)
    {
        uint4 z = make_uint4(0, 0, 0, 0);
        uint4* xb = (uint4*)(smem + O_XR);
        for (int i = tid; i < 1536; i += NTHR) xb[i] = z;
    }
    const int hcol0 = hc0 + tg * 2;

#pragma unroll 1
    for (int layer = 0; layer < L; ++layer) {
        __syncthreads();   // rejoin halves; prev layer fully done

        // ---- stage weights (fp16) into swizzled tiles (full block) ----
        if (layer == 0) {
            for (int i = tid; i < H * 32; i += NTHR) {
                int m = i >> 5, k = i & 31;
                float w = (k < IN_F) ? Wih0[m * IN_F + k] : 0.0f;
                *(__half*)(smem + O_WIH + swz(m, k)) = __float2half_rn(w);
            }
        } else {
            const float* Wl = Wih + (layer - 1) * H * H;
            for (int i = tid; i < H * H; i += NTHR) {
                int m = i >> 7, k = i & 127;
                *(__half*)(smem + O_WIH + swz(m, k)) = __float2half_rn(Wl[i]);
            }
        }
        {
            const float* Wr = Whh + layer * H * H;
            for (int i = tid; i < H * H; i += NTHR) {
                int m = i >> 7, k = i & 127;
                *(__half*)(smem + O_WHH + swz(m, k)) = __float2half_rn(Wr[i]);
            }
        }
        const int rdp = (layer - 1) & 1, wrp = layer & 1;
        const int nkx = (layer == 0) ? 2 : 8;
        float bs0[2], bs1[2];
#pragma unroll
        for (int nt = 0; nt < 2; ++nt) {
            bs0[nt] = bih[layer * H + hcol0 + nt * 8] + bhh[layer * H + hcol0 + nt * 8];
            bs1[nt] = bih[layer * H + hcol0 + nt * 8 + 1] + bhh[layer * H + hcol0 + nt * 8 + 1];
        }
        __syncthreads();   // weights staged

        // ---- load weight fragments ----
        u32 wih[8][2][2], whh[8][2][2];
#pragma unroll
        for (int kc = 0; kc < 8; ++kc)
#pragma unroll
            for (int nt = 0; nt < 2; ++nt) {
                u32 o = swz(hc0 + nt * 8 + (l15 & 7), kc * 16 + ((l15 >> 3) << 3));
                ldsm2(wih[kc][nt], sbase + O_WIH + o);
                ldsm2(whh[kc][nt], sbase + O_WHH + o);
            }

        // ---- prologue: stage X[0], X[1] (this half's rows) ----
        if (layer == 0) {
#pragma unroll
            for (int tt = 0; tt < 2; ++tt)
                for (int i = tid256; i < 512; i += 256) {
                    int b = brow0 + (i >> 5), k = i & 31;
                    if (k < IN_F) {
                        float v = x[((bBase + b) * T + tt) * IN_F + k];
                        *(__half*)(smem + O_XR + tt * 8192 + swz(b, k)) = __float2half_rn(v);
                    }
                }
        } else {
#pragma unroll
            for (int tt = 0; tt < 2; ++tt) {
                u32 d = sbase + O_XR + tt * 8192 + (u32)(brow0 * 16 + tid256) * 16;
                const char* s = (const char*)(g_act[rdp] + (u32)(blockIdx.x * T + tt) * 512
                                              + brow0 * 16) + tid256 * 16;
                CP_ASYNC16(d, s);
            }
            CP_COMMIT();
            CP_WAIT0();
        }
        barh(barid);

        // ---- xp[0] ----
        float xp[2][4];
#pragma unroll
        for (int nt = 0; nt < 2; ++nt) {
            xp[nt][0] = bs0[nt]; xp[nt][1] = bs1[nt];
            xp[nt][2] = bs0[nt]; xp[nt][3] = bs1[nt];
        }
#pragma unroll
        for (int kc = 0; kc < 8; ++kc)
            if (kc < nkx) {
                u32 a4[4];
                ldsm4(a4, sbase + O_XR + aoff[kc]);
                mma16816(xp[0], a4, wih[kc][0]);
                mma16816(xp[1], a4, wih[kc][1]);
            }

        int sw = 2, sr = 1;   // ring slots: write X[t+2], read X[t+1]
#pragma unroll 1
        for (int t = 0; t < T; ++t) {
            const u32 hprev_off = (t & 1) ? O_H0 : O_H1;
            const u32 hwr_off   = (t & 1) ? O_H1 : O_H0;
            const bool doStage = (t + 2 < T);

            // 1. issue staging of X[t+2]
            float lr0 = 0.0f, lr1 = 0.0f;
            if (doStage) {
                if (layer == 0) {
                    int k0 = tid256 & 31;
                    int b0r = brow0 + (tid256 >> 5), b1r = b0r + 8;
                    if (k0 < IN_F) {
                        lr0 = x[((bBase + b0r) * T + t + 2) * IN_F + k0];
                        lr1 = x[((bBase + b1r) * T + t + 2) * IN_F + k0];
                    }
                } else {
                    u32 d = sbase + O_XR + sw * 8192 + (u32)(brow0 * 16 + tid256) * 16;
                    const char* s = (const char*)(g_act[rdp]
                        + (u32)(blockIdx.x * T + t + 2) * 512 + brow0 * 16) + tid256 * 16;
                    CP_ASYNC16(d, s);
                    CP_COMMIT();
                }
            }

            // 2. recurrent chain (critical path)
            float ah[2][4];
#pragma unroll
            for (int nt = 0; nt < 2; ++nt)
#pragma unroll
                for (int j = 0; j < 4; ++j) ah[nt][j] = 0.0f;
            if (t > 0) {
#pragma unroll
                for (int kc = 0; kc < 8; ++kc) {
                    u32 a4[4];
                    ldsm4(a4, sbase + hprev_off + aoff[kc]);
                    mma16816(ah[0], a4, whh[kc][0]);
                    mma16816(ah[1], a4, whh[kc][1]);
                }
            }

            // 3. xp[t+1] (off critical path; X[t+1] staged at t-1)
            float axn[2][4];
            if (t + 1 < T) {
#pragma unroll
                for (int nt = 0; nt < 2; ++nt) {
                    axn[nt][0] = bs0[nt]; axn[nt][1] = bs1[nt];
                    axn[nt][2] = bs0[nt]; axn[nt][3] = bs1[nt];
                }
                const u32 xrd = sbase + O_XR + sr * 8192;
#pragma unroll
                for (int kc = 0; kc < 8; ++kc)
                    if (kc < nkx) {
                        u32 a4[4];
                        ldsm4(a4, xrd + aoff[kc]);
                        mma16816(axn[0], a4, wih[kc][0]);
                        mma16816(axn[1], a4, wih[kc][1]);
                    }
            }

            // 4. layer-0 STS of X[t+2]
            if (doStage && layer == 0) {
                int k0 = tid256 & 31;
                int b0r = brow0 + (tid256 >> 5), b1r = b0r + 8;
                if (k0 < IN_F) {
                    *(__half*)(smem + O_XR + sw * 8192 + swz(b0r, k0)) = __float2half_rn(lr0);
                    *(__half*)(smem + O_XR + sw * 8192 + swz(b1r, k0)) = __float2half_rn(lr1);
                }
            }

            // 5. epilogue: merge + f32 tanh + pack + stores
            char* gdst = (char*)(g_act[wrp] + (u32)(blockIdx.x * T + t) * 512);
#pragma unroll
            for (int nt = 0; nt < 2; ++nt)
#pragma unroll
                for (int bs = 0; bs < 2; ++bs) {
                    float v0 = htanh(xp[nt][bs * 2 + 0] + ah[nt][bs * 2 + 0]);
                    float v1 = htanh(xp[nt][bs * 2 + 1] + ah[nt][bs * 2 + 1]);
                    u32 hp = pack_h2(v0, v1);
                    u32 o = eoff[nt][bs];
                    *(u32*)(smem + hwr_off + o) = hp;
                    if (layer < L - 1)
                        *(u32*)(gdst + o) = hp;
                    if (layer == L - 1 && t == T - 1) {
                        const int b = brow0 + bs * 8 + g;
                        const int hcol = hc0 + nt * 8 + tg * 2;
                        ((float*)(smem + O_HF))[b * H + hcol] = v0;
                        ((float*)(smem + O_HF))[b * H + hcol + 1] = v1;
                    }
                }

            // 6. carry xp
            if (t + 1 < T) {
#pragma unroll
                for (int nt = 0; nt < 2; ++nt)
#pragma unroll
                    for (int j = 0; j < 4; ++j) xp[nt][j] = axn[nt][j];
            }

            // 7. drain staging, 8. step barrier
            if (doStage && layer > 0) CP_WAIT0();
            barh(barid);

            sr = sw;
            sw = (sw + 1 == 3) ? 0 : sw + 1;
        }
    }

    __syncthreads();   // both halves' O_HF writes visible

    // ---- FC on last hidden state ----
    const float* hf = (const float*)(smem + O_HF);
    for (int i = tid; i < BT * C; i += NTHR) {
        int b = i / C, c = i - b * C;
        float acc = fcb[c];
        const float* w = fcW + c * H;
        const float* hr = hf + b * H;
#pragma unroll 8
        for (int k = 0; k < H; ++k) acc = fmaf(hr[k], w[k], acc);
        out[(bBase + b) * C + c] = acc;
    }
}

extern "C" void kernel_launch(void* const* d_in, const int* in_sizes, int n_in,
                              void* d_out, int out_size) {
    const float* x    = (const float*)d_in[0];
    const float* Wih0 = (const float*)d_in[1];
    const float* Wih  = (const float*)d_in[2];
    const float* Whh  = (const float*)d_in[3];
    const float* bih  = (const float*)d_in[4];
    const float* bhh  = (const float*)d_in[5];
    const float* fcW  = (const float*)d_in[6];
    const float* fcb  = (const float*)d_in[7];
    cudaFuncSetAttribute(rnn_mma, cudaFuncAttributeMaxDynamicSharedMemorySize, SMEM_BYTES);
    rnn_mma<<<NBLK, NTHR, SMEM_BYTES>>>(x, Wih0, Wih, Whh, bih, bhh, fcW, fcb, (float*)d_out);
}